// round 3
// baseline (speedup 1.0000x reference)
#include <cuda_runtime.h>
#include <math.h>

#define BATCH   64
#define IN_F    512
#define OUT_F   512

// Scratch (no allocations allowed -> __device__ globals)
__device__ float gW[OUT_F * IN_F];        // scaled, masked w
__device__ float gA[8 * 64 * 64];         // gA[d][i][o] = exp(g[d,o,i])

// ---------------------------------------------------------------------------
// K1: per-row weight prep. One block (128 thr) per row r of W.
// ---------------------------------------------------------------------------
__global__ void __launch_bounds__(128) k_weights(const float* __restrict__ W,
                                                 const float* __restrict__ diag_w) {
    const int r   = blockIdx.x;
    const int rb  = r >> 6;
    const int lo  = rb << 6;
    const int hi  = lo + 64;
    const int tid = threadIdx.x;

    // one float4 per thread covers the row (128*4 = 512)
    const float4 wv4 = ((const float4*)(W + r * IN_F))[tid];
    float wv[4] = {wv4.x, wv4.y, wv4.z, wv4.w};
    float wu[4];
    float ss = 0.f;
    #pragma unroll
    for (int j = 0; j < 4; j++) {
        const int c = tid * 4 + j;
        float u;
        if (c >= hi)      u = 0.f;
        else if (c >= lo) u = __expf(wv[j]);
        else              u = wv[j];
        wu[j] = u;
        ss += u * u;
    }
    #pragma unroll
    for (int off = 16; off > 0; off >>= 1)
        ss += __shfl_down_sync(0xffffffffu, ss, off);
    __shared__ float sred[4];
    __shared__ float sbc[2];
    if ((tid & 31) == 0) sred[tid >> 5] = ss;
    __syncthreads();
    if (tid == 0) {
        const float wsn = sred[0] + sred[1] + sred[2] + sred[3];
        const float dv  = diag_w[r];
        sbc[0] = __expf(dv) * rsqrtf(wsn);       // row scale for w
        sbc[1] = dv - 0.5f * __logf(wsn);        // c1 for g
    }
    __syncthreads();
    const float scale = sbc[0];
    const float c1    = sbc[1];
    float4 o4 = make_float4(scale * wu[0], scale * wu[1], scale * wu[2], scale * wu[3]);
    ((float4*)(gW + r * IN_F))[tid] = o4;
    #pragma unroll
    for (int j = 0; j < 4; j++) {
        const int c = tid * 4 + j;
        if (c >= lo && c < hi) {
            const int i = c - lo;
            gA[(rb * 64 + i) * 64 + (r - lo)] = __expf(c1 + wv[j]);   // [d][i][o]
        }
    }
}

// ---------------------------------------------------------------------------
// K2 fused, 128 threads:
//   bid <  64 : out tile (8b x 64r, full K=512, bias inline)
//   bid >= 64 : jac for (b,d) pair jbid = bid-64; 4o x 8k register tiles
// ---------------------------------------------------------------------------
__global__ void __launch_bounds__(128) k_main(
        const float* __restrict__ grad,
        const float* __restrict__ inputs,
        const float* __restrict__ bias,
        float* __restrict__ outp) {
    __shared__ float smemBuf[8192];      // jac: As(4096)+Bs(4096); out: sW+sIn
    const int bid = blockIdx.x;
    const int tid = threadIdx.x;

    if (bid >= 64) {
        // ---------------- jac: C = gA[d]^T @ exp(grad_b);  log ----------------
        const int jbid = bid - 64;       // = b*8 + d
        const int d    = jbid & 7;
        float* As = smemBuf;             // [i][o]  (64x64)
        float* Bs = smemBuf + 4096;      // [i][k]  (64x64)

        const float4* a4 = (const float4*)(gA + d * 4096);
        const float4* g4 = (const float4*)(grad + jbid * 4096);
        float4* As4 = (float4*)As;
        float4* Bs4 = (float4*)Bs;
        #pragma unroll
        for (int idx = tid; idx < 1024; idx += 128) {
            As4[idx] = a4[idx];
            const float4 v = g4[idx];
            Bs4[idx] = make_float4(__expf(v.x), __expf(v.y), __expf(v.z), __expf(v.w));
        }
        __syncthreads();

        const int o_t = (tid & 15) * 4;  // 16 -> 64 o
        const int k_t = (tid >> 4) * 8;  // 8  -> 64 k
        float acc[4][8];
        #pragma unroll
        for (int oi = 0; oi < 4; oi++)
            #pragma unroll
            for (int kj = 0; kj < 8; kj++) acc[oi][kj] = 0.f;

        const float* ap = As + o_t;
        const float* bp = Bs + k_t;
        #pragma unroll 4
        for (int ii = 0; ii < 64; ii++) {
            const float4 a  = *(const float4*)(ap + ii * 64);
            const float4 b0 = *(const float4*)(bp + ii * 64);
            const float4 b1 = *(const float4*)(bp + ii * 64 + 4);
            const float av[4] = {a.x, a.y, a.z, a.w};
            const float bv[8] = {b0.x, b0.y, b0.z, b0.w, b1.x, b1.y, b1.z, b1.w};
            #pragma unroll
            for (int oi = 0; oi < 4; oi++)
                #pragma unroll
                for (int kj = 0; kj < 8; kj++)
                    acc[oi][kj] += av[oi] * bv[kj];
        }

        float* jb = outp + 32768 + jbid * 4096;   // jac block [o][k]
        #pragma unroll
        for (int oi = 0; oi < 4; oi++) {
            float4 v0 = make_float4(__logf(acc[oi][0]), __logf(acc[oi][1]),
                                    __logf(acc[oi][2]), __logf(acc[oi][3]));
            float4 v1 = make_float4(__logf(acc[oi][4]), __logf(acc[oi][5]),
                                    __logf(acc[oi][6]), __logf(acc[oi][7]));
            float* row = jb + (o_t + oi) * 64 + k_t;
            *(float4*)row       = v0;
            *(float4*)(row + 4) = v1;
        }
    } else {
        // ---------------- out = inputs @ w^T + bias ----------------
        float* sW  = smemBuf;            // [64][65] padded  (r-major)
        float* sIn = smemBuf + 64 * 65;  // [8][64]
        const int rt = bid >> 3;         // r-tile
        const int bt = bid & 7;          // batch-tile (8 rows)
        const int b  = tid >> 4;         // 0..7
        const int r4 = (tid & 15) * 4;   // 0..60
        float acc[4] = {0.f, 0.f, 0.f, 0.f};

        for (int kc = 0; kc < 8; kc++) {
            #pragma unroll
            for (int idx = tid; idx < 1024; idx += 128) {   // float4 tile loads
                const int row = idx >> 4, c4 = (idx & 15) * 4;
                const float4 v = *(const float4*)(gW + (rt * 64 + row) * IN_F + kc * 64 + c4);
                float* dst = sW + row * 65 + c4;
                dst[0] = v.x; dst[1] = v.y; dst[2] = v.z; dst[3] = v.w;
            }
            for (int idx = tid; idx < 128; idx += 128) {    // 8x64 / 4
                const int row = idx >> 4, c4 = (idx & 15) * 4;
                const float4 v = *(const float4*)(inputs + (bt * 8 + row) * IN_F + kc * 64 + c4);
                float* dst = sIn + row * 64 + c4;
                dst[0] = v.x; dst[1] = v.y; dst[2] = v.z; dst[3] = v.w;
            }
            __syncthreads();
            #pragma unroll 8
            for (int kk = 0; kk < 64; kk++) {
                const float iv = sIn[b * 64 + kk];
                #pragma unroll
                for (int j = 0; j < 4; j++)
                    acc[j] += iv * sW[(r4 + j) * 65 + kk];
            }
            __syncthreads();
        }
        const int r = rt * 64 + r4;
        float* orow = outp + (bt * 8 + b) * OUT_F + r;
        #pragma unroll
        for (int j = 0; j < 4; j++) orow[j] = acc[j] + bias[r + j];
    }
}

// ---------------------------------------------------------------------------
// inputs: [0] inputs (64x512 f32), [1] grad (64x8x64x64 f32),
//         [2] W (512x512 f32), [3] diag_w (512 f32), [4] bias (512 f32)
// d_out:  out (64x512) followed by jac (64x8x64x64), f32
// ---------------------------------------------------------------------------
extern "C" void kernel_launch(void* const* d_in, const int* in_sizes, int n_in,
                              void* d_out, int out_size) {
    const float* inputs = (const float*)d_in[0];
    const float* grad   = (const float*)d_in[1];
    const float* W      = (const float*)d_in[2];
    const float* diag_w = (const float*)d_in[3];
    const float* bias   = (const float*)d_in[4];
    float* outp = (float*)d_out;

    k_weights<<<512, 128>>>(W, diag_w);
    k_main<<<512 + 64, 128>>>(grad, inputs, bias, outp);
}